// round 1
// baseline (speedup 1.0000x reference)
#include <cuda_runtime.h>
#include <math.h>

// Problem shape (fixed by the reference): B=2, S=4096, H=1024, M=B*S=8192
#define BDIM 2
#define SDIM 4096
#define HDIM 1024
#define MDIM 8192

#define BM 128
#define BN 128
#define BK 8

// Scratch (device globals: allocation inside kernel_launch is forbidden)
__device__ float g_q[(size_t)MDIM * HDIM];      // 32 MB
__device__ float g_k[(size_t)MDIM * HDIM];      // 32 MB
__device__ float g_v[(size_t)MDIM * HDIM];      // 32 MB
__device__ float g_attn[(size_t)MDIM * HDIM];   // 32 MB
__device__ float g_s[(size_t)BDIM * SDIM * SDIM]; // 128 MB

// ---------------------------------------------------------------------------
// NT GEMM: C[m,n] = alpha * sum_k A[m,k]*B[n,k] + bias[n]
// A: [M,K] row-major, B: [N,K] row-major (both K-contiguous).
// Requires M%128==0, N%128==0, K%8==0 (true for all shapes here).
// Batched via blockIdx.z with element strides sA/sB/sC.
// ---------------------------------------------------------------------------
__global__ __launch_bounds__(256)
void gemm_nt(const float* __restrict__ A, const float* __restrict__ B,
             const float* __restrict__ bias, float* __restrict__ C,
             int M, int N, int K, float alpha,
             long long sA, long long sB, long long sC)
{
    A += (long long)blockIdx.z * sA;
    B += (long long)blockIdx.z * sB;
    C += (long long)blockIdx.z * sC;

    __shared__ float As[BK][BM];
    __shared__ float Bs[BK][BN];

    const int tid = threadIdx.x;
    const int tx = tid & 15;   // 0..15 -> column groups
    const int ty = tid >> 4;   // 0..15 -> row groups

    const int m0 = blockIdx.y * BM;
    const int n0 = blockIdx.x * BN;

    // Global load mapping: one float4 of A-tile and one of B-tile per thread.
    const int lrow = tid >> 1;          // 0..127
    const int lcol = (tid & 1) * 4;     // 0 or 4

    const float* Aptr = A + (long long)(m0 + lrow) * K + lcol;
    const float* Bptr = B + (long long)(n0 + lrow) * K + lcol;

    float acc[8][8];
    #pragma unroll
    for (int i = 0; i < 8; i++)
        #pragma unroll
        for (int j = 0; j < 8; j++) acc[i][j] = 0.f;

    for (int k0 = 0; k0 < K; k0 += BK) {
        float4 av = *reinterpret_cast<const float4*>(Aptr + k0);
        float4 bv = *reinterpret_cast<const float4*>(Bptr + k0);
        As[lcol + 0][lrow] = av.x; As[lcol + 1][lrow] = av.y;
        As[lcol + 2][lrow] = av.z; As[lcol + 3][lrow] = av.w;
        Bs[lcol + 0][lrow] = bv.x; Bs[lcol + 1][lrow] = bv.y;
        Bs[lcol + 2][lrow] = bv.z; Bs[lcol + 3][lrow] = bv.w;
        __syncthreads();

        #pragma unroll
        for (int kk = 0; kk < BK; ++kk) {
            const float4* As4 = reinterpret_cast<const float4*>(As[kk]);
            const float4* Bs4 = reinterpret_cast<const float4*>(Bs[kk]);
            float4 a0 = As4[ty], a1 = As4[ty + 16];   // rows ty*4.. and 64+ty*4..
            float4 b0 = Bs4[tx], b1 = Bs4[tx + 16];   // cols tx*4.. and 64+tx*4..
            float ra[8] = {a0.x, a0.y, a0.z, a0.w, a1.x, a1.y, a1.z, a1.w};
            float rb[8] = {b0.x, b0.y, b0.z, b0.w, b1.x, b1.y, b1.z, b1.w};
            #pragma unroll
            for (int i = 0; i < 8; i++)
                #pragma unroll
                for (int j = 0; j < 8; j++)
                    acc[i][j] += ra[i] * rb[j];
        }
        __syncthreads();
    }

    // Bias into registers (per output column)
    float bb[8];
    #pragma unroll
    for (int jh = 0; jh < 2; jh++) {
        int n = n0 + jh * 64 + tx * 4;
        if (bias) {
            float4 b = *reinterpret_cast<const float4*>(bias + n);
            bb[jh*4+0] = b.x; bb[jh*4+1] = b.y; bb[jh*4+2] = b.z; bb[jh*4+3] = b.w;
        } else {
            bb[jh*4+0] = bb[jh*4+1] = bb[jh*4+2] = bb[jh*4+3] = 0.f;
        }
    }

    #pragma unroll
    for (int ih = 0; ih < 2; ih++) {
        #pragma unroll
        for (int ii = 0; ii < 4; ii++) {
            int m = m0 + ih * 64 + ty * 4 + ii;
            float* Crow = C + (long long)m * N;
            #pragma unroll
            for (int jh = 0; jh < 2; jh++) {
                int n = n0 + jh * 64 + tx * 4;
                float4 o;
                o.x = alpha * acc[ih*4+ii][jh*4+0] + bb[jh*4+0];
                o.y = alpha * acc[ih*4+ii][jh*4+1] + bb[jh*4+1];
                o.z = alpha * acc[ih*4+ii][jh*4+2] + bb[jh*4+2];
                o.w = alpha * acc[ih*4+ii][jh*4+3] + bb[jh*4+3];
                *reinterpret_cast<float4*>(Crow + n) = o;
            }
        }
    }
}

// ---------------------------------------------------------------------------
// NN GEMM: C[m,n] = sum_k A[m,k]*B[k,n]   (A:[M,K], B:[K,N], both row-major)
// ---------------------------------------------------------------------------
__global__ __launch_bounds__(256)
void gemm_nn(const float* __restrict__ A, const float* __restrict__ B,
             float* __restrict__ C,
             int M, int N, int K,
             long long sA, long long sB, long long sC)
{
    A += (long long)blockIdx.z * sA;
    B += (long long)blockIdx.z * sB;
    C += (long long)blockIdx.z * sC;

    __shared__ float As[BK][BM];
    __shared__ float Bs[BK][BN];

    const int tid = threadIdx.x;
    const int tx = tid & 15;
    const int ty = tid >> 4;

    const int m0 = blockIdx.y * BM;
    const int n0 = blockIdx.x * BN;

    // A load (transpose into smem): one float4 per thread
    const int larow = tid >> 1;
    const int lacol = (tid & 1) * 4;
    // B load (direct, coalesced): 8 rows x 128 cols = 256 float4
    const int lbrow = tid >> 5;          // 0..7
    const int lbcol = (tid & 31) * 4;    // 0..124

    const float* Aptr = A + (long long)(m0 + larow) * K + lacol;
    const float* Bptr = B + (long long)lbrow * N + n0 + lbcol;

    float acc[8][8];
    #pragma unroll
    for (int i = 0; i < 8; i++)
        #pragma unroll
        for (int j = 0; j < 8; j++) acc[i][j] = 0.f;

    for (int k0 = 0; k0 < K; k0 += BK) {
        float4 av = *reinterpret_cast<const float4*>(Aptr + k0);
        float4 bv = *reinterpret_cast<const float4*>(Bptr + (long long)k0 * N);
        As[lacol + 0][larow] = av.x; As[lacol + 1][larow] = av.y;
        As[lacol + 2][larow] = av.z; As[lacol + 3][larow] = av.w;
        *reinterpret_cast<float4*>(&Bs[lbrow][lbcol]) = bv;
        __syncthreads();

        #pragma unroll
        for (int kk = 0; kk < BK; ++kk) {
            const float4* As4 = reinterpret_cast<const float4*>(As[kk]);
            const float4* Bs4 = reinterpret_cast<const float4*>(Bs[kk]);
            float4 a0 = As4[ty], a1 = As4[ty + 16];
            float4 b0 = Bs4[tx], b1 = Bs4[tx + 16];
            float ra[8] = {a0.x, a0.y, a0.z, a0.w, a1.x, a1.y, a1.z, a1.w};
            float rb[8] = {b0.x, b0.y, b0.z, b0.w, b1.x, b1.y, b1.z, b1.w};
            #pragma unroll
            for (int i = 0; i < 8; i++)
                #pragma unroll
                for (int j = 0; j < 8; j++)
                    acc[i][j] += ra[i] * rb[j];
        }
        __syncthreads();
    }

    #pragma unroll
    for (int ih = 0; ih < 2; ih++) {
        #pragma unroll
        for (int ii = 0; ii < 4; ii++) {
            int m = m0 + ih * 64 + ty * 4 + ii;
            float* Crow = C + (long long)m * N;
            #pragma unroll
            for (int jh = 0; jh < 2; jh++) {
                int n = n0 + jh * 64 + tx * 4;
                float4 o;
                o.x = acc[ih*4+ii][jh*4+0];
                o.y = acc[ih*4+ii][jh*4+1];
                o.z = acc[ih*4+ii][jh*4+2];
                o.w = acc[ih*4+ii][jh*4+3];
                *reinterpret_cast<float4*>(Crow + n) = o;
            }
        }
    }
}

// ---------------------------------------------------------------------------
// Row softmax over 4096 columns, one block (256 threads) per row.
// ---------------------------------------------------------------------------
__device__ __forceinline__ float warp_max(float v) {
    #pragma unroll
    for (int o = 16; o > 0; o >>= 1) v = fmaxf(v, __shfl_xor_sync(0xffffffffu, v, o));
    return v;
}
__device__ __forceinline__ float warp_sum(float v) {
    #pragma unroll
    for (int o = 16; o > 0; o >>= 1) v += __shfl_xor_sync(0xffffffffu, v, o);
    return v;
}

__global__ __launch_bounds__(256)
void softmax_rows(float* __restrict__ S)
{
    const int tid = threadIdx.x;
    float* r = S + (size_t)blockIdx.x * SDIM;

    __shared__ float red[8];

    float v[16];
    float mx = -1e30f;
    #pragma unroll
    for (int i = 0; i < 16; i++) {
        v[i] = r[tid + i * 256];
        mx = fmaxf(mx, v[i]);
    }
    mx = warp_max(mx);
    if ((tid & 31) == 0) red[tid >> 5] = mx;
    __syncthreads();
    {
        float t = (tid < 8) ? red[tid] : -1e30f;
        t = warp_max(t);
        if (tid == 0) red[0] = t;
    }
    __syncthreads();
    mx = red[0];
    __syncthreads();

    float sum = 0.f;
    #pragma unroll
    for (int i = 0; i < 16; i++) {
        v[i] = __expf(v[i] - mx);
        sum += v[i];
    }
    sum = warp_sum(sum);
    if ((tid & 31) == 0) red[tid >> 5] = sum;
    __syncthreads();
    {
        float t = (tid < 8) ? red[tid] : 0.f;
        t = warp_sum(t);
        if (tid == 0) red[0] = t;
    }
    __syncthreads();
    const float inv = 1.f / red[0];

    #pragma unroll
    for (int i = 0; i < 16; i++)
        r[tid + i * 256] = v[i] * inv;
}

// ---------------------------------------------------------------------------
// Launch
// ---------------------------------------------------------------------------
extern "C" void kernel_launch(void* const* d_in, const int* in_sizes, int n_in,
                              void* d_out, int out_size)
{
    const float* x  = (const float*)d_in[0];
    const float* Wq = (const float*)d_in[1];
    const float* bq = (const float*)d_in[2];
    const float* Wk = (const float*)d_in[3];
    const float* bk = (const float*)d_in[4];
    const float* Wv = (const float*)d_in[5];
    const float* bv = (const float*)d_in[6];
    const float* Wo = (const float*)d_in[7];
    const float* bo = (const float*)d_in[8];
    float* out = (float*)d_out;

    float* q = g_q;
    float* k = g_k;
    float* v = g_v;
    float* attn = g_attn;
    float* s = g_s;
    // Resolve device-global addresses via kernel parameters directly (device
    // symbols are directly usable as pointers in device code; here we pass the
    // symbol addresses, valid because __device__ globals have device addresses
    // identical in the unified address space on sm_103a).

    const dim3 blk(256);

    // QKV projections: [8192,1024] = x[8192,1024] * W^T + b
    dim3 gproj(HDIM / BN, MDIM / BM, 1);   // (8, 64)
    gemm_nt<<<gproj, blk>>>(x, Wq, bq, q, MDIM, HDIM, HDIM, 1.f, 0, 0, 0);
    gemm_nt<<<gproj, blk>>>(x, Wk, bk, k, MDIM, HDIM, HDIM, 1.f, 0, 0, 0);
    gemm_nt<<<gproj, blk>>>(x, Wv, bv, v, MDIM, HDIM, HDIM, 1.f, 0, 0, 0);

    // scores = Q K^T / 8  (per batch)
    dim3 gsc(SDIM / BN, SDIM / BM, BDIM);  // (32, 32, 2)
    gemm_nt<<<gsc, blk>>>(q, k, nullptr, s, SDIM, SDIM, HDIM, 0.125f,
                          (long long)SDIM * HDIM, (long long)SDIM * HDIM,
                          (long long)SDIM * SDIM);

    // softmax over rows (both batches flattened: 8192 rows of 4096)
    softmax_rows<<<BDIM * SDIM, blk>>>(s);

    // attn = P V  (per batch)
    dim3 gpv(HDIM / BN, SDIM / BM, BDIM);  // (8, 32, 2)
    gemm_nn<<<gpv, blk>>>(s, v, attn, SDIM, HDIM, SDIM,
                          (long long)SDIM * SDIM, (long long)SDIM * HDIM,
                          (long long)SDIM * HDIM);

    // out = attn Wo^T + bo
    gemm_nt<<<gproj, blk>>>(attn, Wo, bo, out, MDIM, HDIM, HDIM, 1.f, 0, 0, 0);
}